// round 1
// baseline (speedup 1.0000x reference)
#include <cuda_runtime.h>
#include <cuda_bf16.h>

// KTVLoss: windowed-L1 gradient normalization loss + L1 grad matching loss.
// Shapes: 3 inputs (8,3,512,512) fp32; output scalar fp32.
//
// Pipeline (all in one graph-capturable launch sequence):
//   k_zero    : zero double accumulators
//   k_tiles   : per 64x64 tile: load 3 image tiles (+halo) to SMEM, compute
//               separable 10x10 box sums of |gx|,|gy| per image (rolling sums),
//               write 6 windowed-sum arrays to scratch; fused grad-loss L1 sums.
//   k_combine : linear combine of 6 arrays -> ratio -> mean numerator
//   k_final   : scalar assembly

#define HH 512
#define WW 512
#define TS 64          // output tile
#define TLD 74         // loaded tile (TS + window-1 + 1 for gradient)
#define TP 76          // tile row pad (floats)
#define CP 77          // colsum row pad (conflict-free)
#define SP 65          // staged S row pad (conflict-free)
#define PLANES 24      // B*C = 8*3
#define SH 502         // windowed rows for x-dir (511-9)
#define SWX 503        // windowed cols for x-dir (512-9)
#define LFLAT 252506   // 502*503 == 503*502
#define NGRAD 6279168.0 // 24*511*512 elements per grad direction

__device__ double g_acc[3];                    // [norm_sum, gx_l1, gy_l1]
__device__ float  g_S[6ull * PLANES * LFLAT];  // Lx,Ly,Rx,Ry,Ix,Iy windowed sums

// |gradient| at local tile coords. DIR=0: vertical diff (gx), DIR=1: horizontal (gy)
template <int DIR>
__device__ __forceinline__ float absg(const float* __restrict__ t, int y, int x) {
    if (DIR == 0) return fabsf(t[(y + 1) * TP + x] - t[y * TP + x]);
    else          return fabsf(t[y * TP + x + 1] - t[y * TP + x]);
}

// One direction's separable 10x10 box sum for one image tile.
// C phase: rolling column sums of |grad| (64 x 73)
// S phase: rolling row sums of C (64 x 64), staged in SMEM
// Store: coalesced bounded write to global scratch
template <int DIR>
__device__ __forceinline__ void boxdir(const float* __restrict__ t,
                                       float* __restrict__ C,
                                       float* __restrict__ S,
                                       float* __restrict__ outBase,
                                       int p, int y0, int x0, int tid) {
    // ---- column sums: 73 columns x 4 row-chunks of 16 ----
    for (int task = tid; task < 73 * 4; task += 256) {
        int x  = task % 73;       // adjacent threads -> adjacent columns (no conflicts)
        int yb = (task / 73) * 16;
        float s = 0.f;
#pragma unroll
        for (int d = 0; d < 10; d++) s += absg<DIR>(t, yb + d, x);
        C[yb * CP + x] = s;
#pragma unroll
        for (int j = 1; j < 16; j++) {
            s += absg<DIR>(t, yb + j + 9, x) - absg<DIR>(t, yb + j - 1, x);
            C[(yb + j) * CP + x] = s;
        }
    }
    __syncthreads();
    // ---- row sums: 64 rows x 4 col-chunks of 16 (exactly 256 tasks) ----
    {
        int y  = tid >> 2;
        int xb = (tid & 3) * 16;
        const float* cr = C + y * CP;
        float s = 0.f;
#pragma unroll
        for (int d = 0; d < 10; d++) s += cr[xb + d];
        S[y * SP + xb] = s;
#pragma unroll
        for (int j = 1; j < 16; j++) {
            s += cr[xb + j + 9] - cr[xb + j - 1];
            S[y * SP + xb + j] = s;
        }
    }
    __syncthreads();
    // ---- coalesced bounded store ----
    const int Hs = (DIR == 0) ? SH : SWX;   // 502 : 503
    const int Ws = (DIR == 0) ? SWX : SH;   // 503 : 502
    float* out = outBase + (size_t)p * LFLAT;
    for (int i = tid; i < TS * TS; i += 256) {
        int y = i >> 6, x = i & 63;
        int gy = y0 + y, gx = x0 + x;
        if (gy < Hs && gx < Ws) out[gy * Ws + gx] = S[y * SP + x];
    }
    __syncthreads();
}

__global__ void __launch_bounds__(256, 2)
k_tiles(const float* __restrict__ Lp, const float* __restrict__ Rp,
        const float* __restrict__ Ip) {
    extern __shared__ float sm[];
    float* T0 = sm;
    float* T1 = sm + TLD * TP;
    float* T2 = sm + 2 * TLD * TP;
    float* C  = sm + 3 * TLD * TP;
    float* S  = C + TS * CP;

    const int tid = threadIdx.x;
    const int p  = blockIdx.z;
    const int y0 = blockIdx.y * TS;
    const int x0 = blockIdx.x * TS;
    const size_t pb = (size_t)p * (HH * WW);

    const float* srcs[3] = {Lp + pb, Rp + pb, Ip + pb};
    float* Ts[3] = {T0, T1, T2};

    // ---- load 3 tiles with halo (OOB -> 0; OOB never feeds a valid output) ----
#pragma unroll
    for (int k = 0; k < 3; k++) {
        const float* im = srcs[k];
        float* t = Ts[k];
        for (int i = tid; i < TLD * TLD; i += 256) {
            int r = i / TLD, c = i - r * TLD;
            int gr = y0 + r, gc = x0 + c;
            t[r * TP + c] = (gr < HH && gc < WW) ? __ldg(im + gr * WW + gc) : 0.f;
        }
    }
    __syncthreads();

    // ---- fused grad loss: |gL+gR-gI| over owned 64x64 region ----
    float axs = 0.f, ays = 0.f;
    for (int i = tid; i < TS * TS; i += 256) {
        int y = i >> 6, x = i & 63;
        int o = y * TP + x;
        float l0 = T0[o], r0 = T1[o], i0 = T2[o];
        if (y0 + y < HH - 1) {
            float d = (T0[o + TP] - l0) + (T1[o + TP] - r0) - (T2[o + TP] - i0);
            axs += fabsf(d);
        }
        if (x0 + x < WW - 1) {
            float d = (T0[o + 1] - l0) + (T1[o + 1] - r0) - (T2[o + 1] - i0);
            ays += fabsf(d);
        }
    }

    // ---- box sums per image, both directions ----
    const size_t AS = (size_t)PLANES * LFLAT;
#pragma unroll
    for (int k = 0; k < 3; k++) {
        boxdir<0>(Ts[k], C, S, g_S + (size_t)(2 * k) * AS,     p, y0, x0, tid);
        boxdir<1>(Ts[k], C, S, g_S + (size_t)(2 * k + 1) * AS, p, y0, x0, tid);
    }

    // ---- block reduce grad sums, double atomics ----
#pragma unroll
    for (int o = 16; o; o >>= 1) {
        axs += __shfl_down_sync(0xffffffffu, axs, o);
        ays += __shfl_down_sync(0xffffffffu, ays, o);
    }
    __shared__ float rx[8], ry[8];
    int w = tid >> 5, ln = tid & 31;
    if (ln == 0) { rx[w] = axs; ry[w] = ays; }
    __syncthreads();
    if (tid == 0) {
        float sx = 0.f, sy = 0.f;
#pragma unroll
        for (int i = 0; i < 8; i++) { sx += rx[i]; sy += ry[i]; }
        atomicAdd(&g_acc[1], (double)sx);
        atomicAdd(&g_acc[2], (double)sy);
    }
}

__global__ void k_zero() {
    if (threadIdx.x < 3) g_acc[threadIdx.x] = 0.0;
}

__global__ void k_combine() {
    const size_t n = (size_t)PLANES * LFLAT;
    const float* __restrict__ s0 = g_S;
    const float* __restrict__ s1 = g_S + n;
    const float* __restrict__ s2 = g_S + 2 * n;
    const float* __restrict__ s3 = g_S + 3 * n;
    const float* __restrict__ s4 = g_S + 4 * n;
    const float* __restrict__ s5 = g_S + 5 * n;

    float acc = 0.f;
    for (size_t i = (size_t)blockIdx.x * blockDim.x + threadIdx.x; i < n;
         i += (size_t)gridDim.x * blockDim.x) {
        float num = (s0[i] + s1[i]) + (s2[i] + s3[i]);
        float den = s4[i] + s5[i] + 1e-4f;  // (Si/100 + 1e-6) * 100, /100 on num cancels
        acc += num / den;
    }
#pragma unroll
    for (int o = 16; o; o >>= 1) acc += __shfl_down_sync(0xffffffffu, acc, o);
    __shared__ float r[8];
    int w = threadIdx.x >> 5, ln = threadIdx.x & 31;
    if (ln == 0) r[w] = acc;
    __syncthreads();
    if (threadIdx.x == 0) {
        float s = 0.f;
#pragma unroll
        for (int i = 0; i < 8; i++) s += r[i];
        atomicAdd(&g_acc[0], (double)s);
    }
}

__global__ void k_final(float* out) {
    if (threadIdx.x == 0) {
        double norm_loss = g_acc[0] / ((double)PLANES * (double)LFLAT);
        double grad_loss = (g_acc[1] + g_acc[2]) / NGRAD;
        out[0] = (float)(1e-4 * norm_loss + grad_loss);
    }
}

extern "C" void kernel_launch(void* const* d_in, const int* in_sizes, int n_in,
                              void* d_out, int out_size) {
    const float* out_l   = (const float*)d_in[0];
    const float* out_r   = (const float*)d_in[1];
    const float* input_i = (const float*)d_in[2];
    float* out = (float*)d_out;

    const int smem = (3 * TLD * TP + TS * CP + TS * SP) * (int)sizeof(float); // 103,840 B
    cudaFuncSetAttribute(k_tiles, cudaFuncAttributeMaxDynamicSharedMemorySize, smem);

    k_zero<<<1, 32>>>();
    k_tiles<<<dim3(8, 8, PLANES), 256, smem>>>(out_l, out_r, input_i);
    k_combine<<<1184, 256>>>();
    k_final<<<1, 32>>>(out);
}

// round 2
// speedup vs baseline: 1.3780x; 1.3780x over previous
#include <cuda_runtime.h>
#include <cuda_fp16.h>

// KTVLoss v2: fused L+R box filters (4 instead of 6), half2-packed (num,den)
// scratch (48.5 MB round-trip instead of 290 MB), ring-buffer rolling sums
// (each |grad| evaluated once).
//
//   k_zero    : zero double accumulators
//   k_tiles   : per 64x64 tile: 3 image tiles+halo in SMEM; per direction:
//               box sum of |gL|+|gR| and of |gI| via separable rolling sums;
//               pack (A,I) as half2, coalesced 4B store; fused grad-loss L1.
//   k_combine : linear uint4 stream of the 2 half2 arrays -> ratio -> sum
//   k_final   : scalar assembly

#define HH 512
#define WW 512
#define TS 64
#define TLD 74         // TS + 9 (window) + 1 (gradient)
#define TP 76          // tile row pad (floats)
#define CP 77          // colsum row pad
#define SP2 66         // half staging row pad (halves)
#define PLANES 24
#define SH 502
#define SWX 503
#define LFLAT 252506   // 502*503 == 503*502
#define NGRAD 6279168.0

__device__ double g_acc[3];                        // [norm_sum, gx_l1, gy_l1]
__device__ unsigned int g_Px[(size_t)PLANES * LFLAT];  // half2 (A_x, I_x)
__device__ unsigned int g_Py[(size_t)PLANES * LFLAT];  // half2 (A_y, I_y)

// Column rolling box-sum (window 10) of |grad|. DIR=0: vertical diff (gx),
// DIR=1: horizontal diff (gy). NIMG=2 sums two images' |grad| pointwise.
// Tasks: 73 columns x 4 row-chunks of 16 outputs. Each grad eval'd once.
template <int DIR, int NIMG>
__device__ __forceinline__ void colsum_pass(const float* __restrict__ t0,
                                            const float* __restrict__ t1,
                                            float* __restrict__ C, int tid) {
    for (int task = tid; task < 73 * 4; task += 256) {
        int x  = task % 73;
        int yb = (task / 73) * 16;
        float s = 0.f, ring[10];
        float a0 = 0.f, a1 = 0.f;
        if (DIR == 0) {
            a0 = t0[yb * TP + x];
            if (NIMG == 2) a1 = t1[yb * TP + x];
        }
#pragma unroll
        for (int j = 0; j < 25; j++) {
            float g;
            if (DIR == 0) {
                float n0 = t0[(yb + j + 1) * TP + x];
                g = fabsf(n0 - a0); a0 = n0;
                if (NIMG == 2) {
                    float n1 = t1[(yb + j + 1) * TP + x];
                    g += fabsf(n1 - a1); a1 = n1;
                }
            } else {
                const float* r0 = t0 + (yb + j) * TP + x;
                g = fabsf(r0[1] - r0[0]);
                if (NIMG == 2) {
                    const float* r1 = t1 + (yb + j) * TP + x;
                    g += fabsf(r1[1] - r1[0]);
                }
            }
            if (j >= 10) s -= ring[j % 10];
            ring[j % 10] = g;
            s += g;
            if (j >= 9) C[(yb + j - 9) * CP + x] = s;
        }
    }
}

// Row rolling box-sum of C -> half staging. Exactly 256 tasks (64 rows x 4 chunks).
__device__ __forceinline__ void rowsum_pass(const float* __restrict__ C,
                                            __half* __restrict__ S, int tid) {
    int y  = tid >> 2;
    int xb = (tid & 3) * 16;
    const float* cr = C + y * CP + xb;
    float s = 0.f, ring[10];
#pragma unroll
    for (int j = 0; j < 25; j++) {
        float g = cr[j];
        if (j >= 10) s -= ring[j % 10];
        ring[j % 10] = g;
        s += g;
        if (j >= 9) S[y * SP2 + xb + j - 9] = __float2half(s);
    }
}

__global__ void __launch_bounds__(256, 2)
k_tiles(const float* __restrict__ Lp, const float* __restrict__ Rp,
        const float* __restrict__ Ip) {
    extern __shared__ float sm[];
    float* T0 = sm;
    float* T1 = sm + TLD * TP;
    float* T2 = sm + 2 * TLD * TP;
    float* C  = sm + 3 * TLD * TP;
    __half* SA = (__half*)(C + TS * CP);           // LR windowed sums
    __half* SI = SA + TS * SP2;                    // I windowed sums

    const int tid = threadIdx.x;
    const int p  = blockIdx.z;
    const int y0 = blockIdx.y * TS;
    const int x0 = blockIdx.x * TS;
    const size_t pb = (size_t)p * (HH * WW);

    // ---- load 3 tiles with halo (OOB -> 0, never feeds a stored output) ----
    {
        const float* srcs[3] = {Lp + pb, Rp + pb, Ip + pb};
        float* Ts[3] = {T0, T1, T2};
#pragma unroll
        for (int k = 0; k < 3; k++) {
            const float* im = srcs[k];
            float* t = Ts[k];
            for (int i = tid; i < TLD * TLD; i += 256) {
                int r = i / TLD, c = i - r * TLD;
                int gr = y0 + r, gc = x0 + c;
                t[r * TP + c] = (gr < HH && gc < WW) ? __ldg(im + gr * WW + gc) : 0.f;
            }
        }
    }
    __syncthreads();

    // ---- fused grad loss over owned 64x64 region ----
    float axs = 0.f, ays = 0.f;
    for (int i = tid; i < TS * TS; i += 256) {
        int y = i >> 6, x = i & 63;
        int o = y * TP + x;
        float l0 = T0[o], r0 = T1[o], i0 = T2[o];
        if (y0 + y < HH - 1) {
            float d = (T0[o + TP] - l0) + (T1[o + TP] - r0) - (T2[o + TP] - i0);
            axs += fabsf(d);
        }
        if (x0 + x < WW - 1) {
            float d = (T0[o + 1] - l0) + (T1[o + 1] - r0) - (T2[o + 1] - i0);
            ays += fabsf(d);
        }
    }

    // ---- DIR 0 (x-map, 502x503) ----
    colsum_pass<0, 2>(T0, T1, C, tid);
    __syncthreads();
    rowsum_pass(C, SA, tid);
    __syncthreads();
    colsum_pass<0, 1>(T2, T2, C, tid);
    __syncthreads();
    rowsum_pass(C, SI, tid);
    __syncthreads();
    {
        unsigned int* out = g_Px + (size_t)p * LFLAT;
        for (int i = tid; i < TS * TS; i += 256) {
            int r = i >> 6, c = i & 63;
            int gy = y0 + r, gx = x0 + c;
            if (gy < SH && gx < SWX) {
                __half2 h = __halves2half2(SA[r * SP2 + c], SI[r * SP2 + c]);
                out[gy * SWX + gx] = *(unsigned int*)&h;
            }
        }
    }
    __syncthreads();

    // ---- DIR 1 (y-map, 503x502) ----
    colsum_pass<1, 2>(T0, T1, C, tid);
    __syncthreads();
    rowsum_pass(C, SA, tid);
    __syncthreads();
    colsum_pass<1, 1>(T2, T2, C, tid);
    __syncthreads();
    rowsum_pass(C, SI, tid);
    __syncthreads();
    {
        unsigned int* out = g_Py + (size_t)p * LFLAT;
        for (int i = tid; i < TS * TS; i += 256) {
            int r = i >> 6, c = i & 63;
            int gy = y0 + r, gx = x0 + c;
            if (gy < SWX && gx < SH) {
                __half2 h = __halves2half2(SA[r * SP2 + c], SI[r * SP2 + c]);
                out[gy * SH + gx] = *(unsigned int*)&h;
            }
        }
    }

    // ---- grad-loss block reduce, double atomics ----
#pragma unroll
    for (int o = 16; o; o >>= 1) {
        axs += __shfl_down_sync(0xffffffffu, axs, o);
        ays += __shfl_down_sync(0xffffffffu, ays, o);
    }
    __shared__ float rx[8], ry[8];
    int w = tid >> 5, ln = tid & 31;
    if (ln == 0) { rx[w] = axs; ry[w] = ays; }
    __syncthreads();
    if (tid == 0) {
        float sx = 0.f, sy = 0.f;
#pragma unroll
        for (int i = 0; i < 8; i++) { sx += rx[i]; sy += ry[i]; }
        atomicAdd(&g_acc[1], (double)sx);
        atomicAdd(&g_acc[2], (double)sy);
    }
}

__global__ void k_zero() {
    if (threadIdx.x < 3) g_acc[threadIdx.x] = 0.0;
}

__device__ __forceinline__ float ratio_term(unsigned int u, unsigned int v) {
    __half2 hu = *(__half2*)&u, hv = *(__half2*)&v;
    float num = __low2float(hu) + __low2float(hv);
    float den = __high2float(hu) + __high2float(hv) + 1e-4f;
    return __fdividef(num, den);
}

__global__ void k_combine() {
    const size_t N4 = ((size_t)PLANES * LFLAT) / 4;  // 1,515,036 uint4 pairs
    const uint4* __restrict__ Px = (const uint4*)g_Px;
    const uint4* __restrict__ Py = (const uint4*)g_Py;

    float acc = 0.f;
    for (size_t i = (size_t)blockIdx.x * blockDim.x + threadIdx.x; i < N4;
         i += (size_t)gridDim.x * blockDim.x) {
        uint4 a = Px[i];
        uint4 b = Py[i];
        acc += ratio_term(a.x, b.x) + ratio_term(a.y, b.y) +
               ratio_term(a.z, b.z) + ratio_term(a.w, b.w);
    }
#pragma unroll
    for (int o = 16; o; o >>= 1) acc += __shfl_down_sync(0xffffffffu, acc, o);
    __shared__ float r[8];
    int w = threadIdx.x >> 5, ln = threadIdx.x & 31;
    if (ln == 0) r[w] = acc;
    __syncthreads();
    if (threadIdx.x == 0) {
        float s = 0.f;
#pragma unroll
        for (int i = 0; i < 8; i++) s += r[i];
        atomicAdd(&g_acc[0], (double)s);
    }
}

__global__ void k_final(float* out) {
    if (threadIdx.x == 0) {
        double norm_loss = g_acc[0] / ((double)PLANES * (double)LFLAT);
        double grad_loss = (g_acc[1] + g_acc[2]) / NGRAD;
        out[0] = (float)(1e-4 * norm_loss + grad_loss);
    }
}

extern "C" void kernel_launch(void* const* d_in, const int* in_sizes, int n_in,
                              void* d_out, int out_size) {
    const float* out_l   = (const float*)d_in[0];
    const float* out_r   = (const float*)d_in[1];
    const float* input_i = (const float*)d_in[2];
    float* out = (float*)d_out;

    const int smem = (3 * TLD * TP + TS * CP) * (int)sizeof(float)
                   + 2 * TS * SP2 * (int)sizeof(__half);  // 104,096 B
    cudaFuncSetAttribute(k_tiles, cudaFuncAttributeMaxDynamicSharedMemorySize, smem);

    k_zero<<<1, 32>>>();
    k_tiles<<<dim3(8, 8, PLANES), 256, smem>>>(out_l, out_r, input_i);
    k_combine<<<1184, 256>>>();
    k_final<<<1, 32>>>(out);
}

// round 5
// speedup vs baseline: 3.8240x; 2.7750x over previous
#include <cuda_runtime.h>
#include <cuda_fp16.h>

// KTVLoss v3: fully-fused band-sweep. No scratch arrays, no combine kernel.
// Each CTA sweeps a horizontal band of one plane, producing x-map rows (s-10)
// and y-map rows (s-9) in lockstep and combining the ratio on the fly
// (flat pairing: i = r*503+x -> y-map row r or r+1).

#define Wimg 512
#define NB 18
#define BROWS 28
#define PLANES 24
#define NWORDS 15932   // total smem words (zeroed)

__device__ float g_part[NB * PLANES][4];

__device__ __forceinline__ unsigned pack2(float a, float b) {
    __half2 h = __floats2half2_rn(a, b);
    return *(unsigned*)&h;
}
__device__ __forceinline__ float2 unpack2(unsigned u) {
    __half2 h = *(__half2*)&u;
    return __half22float2(h);
}
__device__ __forceinline__ __half2 u2h(unsigned u) { return *(__half2*)&u; }
__device__ __forceinline__ unsigned h2u(__half2 h) { return *(unsigned*)&h; }

// Rolling 10-window sums (both half2 lanes = A,I) over src[x0..x0+12],
// 4 outputs -> dst[x0..x0+3], bounded by limit.
__device__ __forceinline__ void window_pass(const unsigned* __restrict__ src,
                                            unsigned* __restrict__ dst,
                                            int x0, int limit) {
    uint4 q0 = *(const uint4*)(src + x0);
    uint4 q1 = *(const uint4*)(src + x0 + 4);
    uint4 q2 = *(const uint4*)(src + x0 + 8);
    unsigned e = src[x0 + 12];
    __half2 a0 = u2h(q0.x), a1 = u2h(q0.y), a2 = u2h(q0.z), a3 = u2h(q0.w);
    __half2 s = __hadd2(__hadd2(__hadd2(a0, a1), __hadd2(a2, a3)),
                __hadd2(__hadd2(__hadd2(u2h(q1.x), u2h(q1.y)),
                                __hadd2(u2h(q1.z), u2h(q1.w))),
                        __hadd2(u2h(q2.x), u2h(q2.y))));
    __half2 o0 = s;
    __half2 o1 = __hsub2(__hadd2(o0, u2h(q2.z)), a0);
    __half2 o2 = __hsub2(__hadd2(o1, u2h(q2.w)), a1);
    __half2 o3 = __hsub2(__hadd2(o2, u2h(e)), a2);
    if (x0 + 3 < limit) {
        *(uint4*)(dst + x0) = make_uint4(h2u(o0), h2u(o1), h2u(o2), h2u(o3));
    } else {
        dst[x0] = h2u(o0);
        if (x0 + 1 < limit) dst[x0 + 1] = h2u(o1);
        if (x0 + 2 < limit) dst[x0 + 2] = h2u(o2);
    }
}

// Combine flat range of x-map row rC with partner y-map values.
__device__ __forceinline__ float combine_row(const unsigned* __restrict__ xw,
                                             const unsigned* __restrict__ YW,
                                             int rC, int t) {
    float a = 0.f;
#pragma unroll
    for (int k = 0; k < 2; k++) {
        int x = t + 256 * k;
        if (x < 503) {
            float2 fx = unpack2(xw[x]);
            int j = rC + x;
            int ry = rC, cy = j;
            if (j >= 502) { ry = rC + 1; cy = j - 502; }
            float2 fy = unpack2(YW[(ry & 3) * 512 + cy]);
            a += __fdividef(fx.x + fy.x, fx.y + fy.y + 1e-4f);
        }
    }
    return a;
}

__global__ void __launch_bounds__(256, 3)
k_main(const float* __restrict__ L, const float* __restrict__ R,
       const float* __restrict__ I) {
    extern __shared__ float sm[];
    float* rawL = sm;                              // 516
    float* rawR = sm + 516;
    float* rawI = sm + 1032;
    unsigned* xr = (unsigned*)(sm + 1548);         // [10][512] half2(gA,gI) vert grads
    unsigned* yr = xr + 5120;                      // [10][512] horiz grads
    unsigned* CX = yr + 5120;                      // 520 colsums half2(A,I)
    unsigned* CY = CX + 520;                       // 520
    unsigned* XW = CY + 520;                       // [2][512] windowed x-rows
    unsigned* YW = XW + 1024;                      // [4][512] windowed y-rows
    float* red = (float*)(YW + 2048);              // 32

    const int t = threadIdx.x;
    const int b = blockIdx.x;
    const int p = blockIdx.y;
    const int r0 = b * BROWS;
    const int r1 = min(502, r0 + BROWS);
    const bool last = (b == NB - 1);
    const int send = r1 + 9;
    const int c1 = 2 * t + 1;

    for (int i = t; i < NWORDS; i += 256) sm[i] = 0.f;
    __syncthreads();

    const size_t pb = (size_t)p * (Wimg * Wimg);
    const float2* Lp = (const float2*)(L + pb);
    const float2* Rp = (const float2*)(R + pb);
    const float2* Ip = (const float2*)(I + pb);

    float2 nl = Lp[r0 * 256 + t], nr = Rp[r0 * 256 + t], ni = Ip[r0 * 256 + t];
    float2 pl = make_float2(0.f, 0.f), pr = pl, pi = pl;
    float sAx0 = 0, sIx0 = 0, sAx1 = 0, sIx1 = 0;
    float sAy0 = 0, sIy0 = 0, sAy1 = 0, sIy1 = 0;
    float accN = 0, accDX = 0, accDY = 0;

    for (int s = r0; s <= send; ++s) {
        float2 cl = nl, cr = nr, ci = ni;
        if (s < send) {
            nl = Lp[(s + 1) * 256 + t];
            nr = Rp[(s + 1) * 256 + t];
            ni = Ip[(s + 1) * 256 + t];
        }
        ((float2*)rawL)[t] = cl;
        ((float2*)rawR)[t] = cr;
        ((float2*)rawI)[t] = ci;

        // vertical grads (gx row s-1)
        unsigned vp0 = 0, vp1 = 0;
        const bool push_x = (s > r0);
        if (push_x) {
            float sl0 = cl.x - pl.x, sl1 = cl.y - pl.y;
            float sr0 = cr.x - pr.x, sr1 = cr.y - pr.y;
            float si0 = ci.x - pi.x, si1 = ci.y - pi.y;
            vp0 = pack2(fabsf(sl0) + fabsf(sr0), fabsf(si0));
            vp1 = pack2(fabsf(sl1) + fabsf(sr1), fabsf(si1));
            if ((s - 1 < r1) || (last && (s - 1) < 511))
                accDX += fabsf(sl0 + sr0 - si0) + fabsf(sl1 + sr1 - si1);
        }
        __syncthreads();  // A: raw row visible

        // horizontal grads (gy row s); neighbor col from smem
        float nbL = rawL[c1 + 1], nbR = rawR[c1 + 1], nbI = rawI[c1 + 1];
        float hl0 = cl.y - cl.x, hl1 = nbL - cl.y;
        float hr0 = cr.y - cr.x, hr1 = nbR - cr.y;
        float hi0 = ci.y - ci.x, hi1 = nbI - ci.y;
        if ((s < r1) || last) {
            float d0 = fabsf(hl0 + hr0 - hi0);
            float d1 = (c1 < 511) ? fabsf(hl1 + hr1 - hi1) : 0.f;
            accDY += d0 + d1;
        }
        // y push (rolling colsum of |gy| over 10 rows)
        {
            unsigned n0 = pack2(fabsf(hl0) + fabsf(hr0), fabsf(hi0));
            unsigned n1 = pack2(fabsf(hl1) + fabsf(hr1), fabsf(hi1));
            uint2* slotp = (uint2*)(yr + (s % 10) * 512) + t;
            uint2 old = *slotp;
            float2 f0 = unpack2(n0), f1 = unpack2(n1);
            float2 o0 = unpack2(old.x), o1 = unpack2(old.y);
            sAy0 += f0.x - o0.x; sIy0 += f0.y - o0.y;
            sAy1 += f1.x - o1.x; sIy1 += f1.y - o1.y;
            *slotp = make_uint2(n0, n1);
            ((uint2*)CY)[t] = make_uint2(pack2(sAy0, sIy0), pack2(sAy1, sIy1));
        }
        // x push
        if (push_x) {
            uint2* slotp = (uint2*)(xr + ((s - 1) % 10) * 512) + t;
            uint2 old = *slotp;
            float2 f0 = unpack2(vp0), f1 = unpack2(vp1);
            float2 o0 = unpack2(old.x), o1 = unpack2(old.y);
            sAx0 += f0.x - o0.x; sIx0 += f0.y - o0.y;
            sAx1 += f1.x - o1.x; sIx1 += f1.y - o1.y;
            *slotp = make_uint2(vp0, vp1);
            ((uint2*)CX)[t] = make_uint2(pack2(sAx0, sIx0), pack2(sAx1, sIx1));
        }
        __syncthreads();  // B: colsums visible

        const int rY = s - 9, rX = s - 10, rC = s - 11;
        if (t < 126 && rY >= r0 && rY <= r1)
            window_pass(CY, YW + (rY & 3) * 512, 4 * t, 502);
        if (t >= 128 && t < 254 && rX >= r0 && rX < r1)
            window_pass(CX, XW + (rX & 1) * 512, 4 * (t - 128), 503);
        if (rC >= r0)
            accN += combine_row(XW + (rC & 1) * 512, YW, rC, t);

        pl = cl; pr = cr; pi = ci;
    }
    __syncthreads();
    {   // last pending x-row
        int rC = r1 - 1;
        accN += combine_row(XW + (rC & 1) * 512, YW, rC, t);
    }

    // block reduce 3 accumulators
#pragma unroll
    for (int o = 16; o; o >>= 1) {
        accN  += __shfl_down_sync(0xffffffffu, accN,  o);
        accDX += __shfl_down_sync(0xffffffffu, accDX, o);
        accDY += __shfl_down_sync(0xffffffffu, accDY, o);
    }
    int w = t >> 5, ln = t & 31;
    if (ln == 0) { red[w] = accN; red[8 + w] = accDX; red[16 + w] = accDY; }
    __syncthreads();
    if (t == 0) {
        float n = 0, dx = 0, dy = 0;
#pragma unroll
        for (int i = 0; i < 8; i++) { n += red[i]; dx += red[8 + i]; dy += red[16 + i]; }
        float* gp = g_part[p * NB + b];
        gp[0] = n; gp[1] = dx; gp[2] = dy;
    }
}

__global__ void k_final(float* out) {
    const int t = threadIdx.x;
    double n = 0, dx = 0, dy = 0;
    for (int i = t; i < NB * PLANES; i += 512) {
        n  += (double)g_part[i][0];
        dx += (double)g_part[i][1];
        dy += (double)g_part[i][2];
    }
#pragma unroll
    for (int o = 16; o; o >>= 1) {
        n  += __shfl_down_sync(0xffffffffu, n,  o);
        dx += __shfl_down_sync(0xffffffffu, dx, o);
        dy += __shfl_down_sync(0xffffffffu, dy, o);
    }
    __shared__ double s0[16], s1[16], s2[16];
    int w = t >> 5, ln = t & 31;
    if (ln == 0) { s0[w] = n; s1[w] = dx; s2[w] = dy; }
    __syncthreads();
    if (t == 0) {
        double N = 0, DX = 0, DY = 0;
#pragma unroll
        for (int i = 0; i < 16; i++) { N += s0[i]; DX += s1[i]; DY += s2[i]; }
        out[0] = (float)(1e-4 * (N / 6060144.0) + (DX + DY) / 6279168.0);
    }
}

extern "C" void kernel_launch(void* const* d_in, const int* in_sizes, int n_in,
                              void* d_out, int out_size) {
    const float* out_l   = (const float*)d_in[0];
    const float* out_r   = (const float*)d_in[1];
    const float* input_i = (const float*)d_in[2];
    float* out = (float*)d_out;

    const int smem = NWORDS * (int)sizeof(float);  // 63,728 B
    cudaFuncSetAttribute(k_main, cudaFuncAttributeMaxDynamicSharedMemorySize, smem);

    k_main<<<dim3(NB, PLANES), 256, smem>>>(out_l, out_r, input_i);
    k_final<<<1, 512>>>(out);
}

// round 16
// speedup vs baseline: 4.1650x; 1.0892x over previous
#include <cuda_runtime.h>
#include <cuda_fp16.h>

// KTVLoss v4: band-sweep with 1 sync/row (shuffle neighbor exchange, no raw-row
// staging), parity-double-buffered colsums, and fused last-CTA finalize.

#define NB 18
#define BROWS 28
#define PLANES 24
#define NCTA (NB * PLANES)
#define NWORDS 15440   // smem words

__device__ float g_part[NCTA][4];
__device__ unsigned g_done;   // zero-init; finalizer resets to 0 every run

__device__ __forceinline__ unsigned pack2(float a, float b) {
    __half2 h = __floats2half2_rn(a, b);
    return *(unsigned*)&h;
}
__device__ __forceinline__ float2 unpack2(unsigned u) {
    __half2 h = *(__half2*)&u;
    return __half22float2(h);
}
__device__ __forceinline__ __half2 u2h(unsigned u) { return *(__half2*)&u; }
__device__ __forceinline__ unsigned h2u(__half2 h) { return *(unsigned*)&h; }

// Rolling 10-window sums (half2 lanes = A,I) over src[x0..x0+12],
// 4 outputs -> dst[x0..x0+3], bounded by limit.
__device__ __forceinline__ void window_pass(const unsigned* __restrict__ src,
                                            unsigned* __restrict__ dst,
                                            int x0, int limit) {
    uint4 q0 = *(const uint4*)(src + x0);
    uint4 q1 = *(const uint4*)(src + x0 + 4);
    uint4 q2 = *(const uint4*)(src + x0 + 8);
    unsigned e = src[x0 + 12];
    __half2 a0 = u2h(q0.x), a1 = u2h(q0.y), a2 = u2h(q0.z), a3 = u2h(q0.w);
    __half2 s = __hadd2(__hadd2(__hadd2(a0, a1), __hadd2(a2, a3)),
                __hadd2(__hadd2(__hadd2(u2h(q1.x), u2h(q1.y)),
                                __hadd2(u2h(q1.z), u2h(q1.w))),
                        __hadd2(u2h(q2.x), u2h(q2.y))));
    __half2 o0 = s;
    __half2 o1 = __hsub2(__hadd2(o0, u2h(q2.z)), a0);
    __half2 o2 = __hsub2(__hadd2(o1, u2h(q2.w)), a1);
    __half2 o3 = __hsub2(__hadd2(o2, u2h(e)), a2);
    if (x0 + 3 < limit) {
        *(uint4*)(dst + x0) = make_uint4(h2u(o0), h2u(o1), h2u(o2), h2u(o3));
    } else {
        dst[x0] = h2u(o0);
        if (x0 + 1 < limit) dst[x0 + 1] = h2u(o1);
        if (x0 + 2 < limit) dst[x0 + 2] = h2u(o2);
    }
}

// Combine flat range of x-map row rC with partner y-map values.
__device__ __forceinline__ float combine_row(const unsigned* __restrict__ xw,
                                             const unsigned* __restrict__ YW,
                                             int rC, int t) {
    float a = 0.f;
#pragma unroll
    for (int k = 0; k < 2; k++) {
        int x = t + 256 * k;
        if (x < 503) {
            float2 fx = unpack2(xw[x]);
            int j = rC + x;
            int ry = rC, cy = j;
            if (j >= 502) { ry = rC + 1; cy = j - 502; }
            float2 fy = unpack2(YW[(ry & 3) * 512 + cy]);
            a += __fdividef(fx.x + fy.x, fx.y + fy.y + 1e-4f);
        }
    }
    return a;
}

__global__ void __launch_bounds__(256, 3)
k_main(const float* __restrict__ L, const float* __restrict__ R,
       const float* __restrict__ I, float* __restrict__ out) {
    extern __shared__ float sm[];
    unsigned* xr = (unsigned*)sm;          // [10][512] vert-grad ring
    unsigned* yr = xr + 5120;              // [10][512] horiz-grad ring
    unsigned* CX = yr + 5120;              // [2][520] parity colsums
    unsigned* CY = CX + 1040;              // [2][520]
    unsigned* XW = CY + 1040;              // [2][512]
    unsigned* YW = XW + 1024;              // [4][512]
    float* red = (float*)(YW + 2048);      // 48 words (reused as 24 doubles)

    const int t = threadIdx.x;
    const int b = blockIdx.x;
    const int p = blockIdx.y;
    const int r0 = b * BROWS;
    const int r1 = min(502, r0 + BROWS);
    const bool last = (b == NB - 1);
    const int send = r1 + 9;
    const int c1 = 2 * t + 1;

    for (int i = t; i < NWORDS; i += 256) sm[i] = 0.f;
    __syncthreads();

    const size_t pb = (size_t)p * (512 * 512);
    const float2* Lp = (const float2*)(L + pb);
    const float2* Rp = (const float2*)(R + pb);
    const float2* Ip = (const float2*)(I + pb);

    float2 nl = Lp[r0 * 256 + t], nr = Rp[r0 * 256 + t], ni = Ip[r0 * 256 + t];
    float2 pl = make_float2(0.f, 0.f), pr = pl, pi = pl;
    float sAx0 = 0, sIx0 = 0, sAx1 = 0, sIx1 = 0;
    float sAy0 = 0, sIy0 = 0, sAy1 = 0, sIy1 = 0;
    float accN = 0, accDX = 0, accDY = 0;

    for (int s = r0; s <= send; ++s) {
        float2 cl = nl, cr = nr, ci = ni;
        if (s < send) {
            nl = Lp[(s + 1) * 256 + t];
            nr = Rp[(s + 1) * 256 + t];
            ni = Ip[(s + 1) * 256 + t];
        }

        // ---- vertical grads (gx row s-1), register-only ----
        unsigned vp0 = 0, vp1 = 0;
        const bool push_x = (s > r0);
        if (push_x) {
            float sl0 = cl.x - pl.x, sl1 = cl.y - pl.y;
            float sr0 = cr.x - pr.x, sr1 = cr.y - pr.y;
            float si0 = ci.x - pi.x, si1 = ci.y - pi.y;
            vp0 = pack2(fabsf(sl0) + fabsf(sr0), fabsf(si0));
            vp1 = pack2(fabsf(sl1) + fabsf(sr1), fabsf(si1));
            if ((s - 1 < r1) || (last && (s - 1) < 511))
                accDX += fabsf(sl0 + sr0 - si0) + fabsf(sl1 + sr1 - si1);
        }

        // ---- horizontal neighbor via shuffle (lane 31: global L1-hit load) ----
        float nbL = __shfl_down_sync(0xffffffffu, cl.x, 1);
        float nbR = __shfl_down_sync(0xffffffffu, cr.x, 1);
        float nbI = __shfl_down_sync(0xffffffffu, ci.x, 1);
        if ((t & 31) == 31) {
            int col = c1 + 1;
            if (col < 512) {
                size_t o = (size_t)s * 512 + col;
                nbL = ((const float*)Lp)[o];
                nbR = ((const float*)Rp)[o];
                nbI = ((const float*)Ip)[o];
            } else { nbL = cl.y; nbR = cr.y; nbI = ci.y; }  // ghost col: zero grads
        }

        float hl0 = cl.y - cl.x, hl1 = nbL - cl.y;
        float hr0 = cr.y - cr.x, hr1 = nbR - cr.y;
        float hi0 = ci.y - ci.x, hi1 = nbI - ci.y;
        if ((s < r1) || last) {
            float d0 = fabsf(hl0 + hr0 - hi0);
            float d1 = (c1 < 511) ? fabsf(hl1 + hr1 - hi1) : 0.f;
            accDY += d0 + d1;
        }

        // ---- y colsum push (ring slots are thread-private) ----
        {
            unsigned n0 = pack2(fabsf(hl0) + fabsf(hr0), fabsf(hi0));
            unsigned n1 = pack2(fabsf(hl1) + fabsf(hr1), fabsf(hi1));
            uint2* slotp = (uint2*)(yr + (s % 10) * 512) + t;
            uint2 old = *slotp;
            float2 f0 = unpack2(n0), f1 = unpack2(n1);
            float2 o0 = unpack2(old.x), o1 = unpack2(old.y);
            sAy0 += f0.x - o0.x; sIy0 += f0.y - o0.y;
            sAy1 += f1.x - o1.x; sIy1 += f1.y - o1.y;
            *slotp = make_uint2(n0, n1);
            ((uint2*)(CY + (s & 1) * 520))[t] =
                make_uint2(pack2(sAy0, sIy0), pack2(sAy1, sIy1));
        }
        // ---- x colsum push ----
        if (push_x) {
            uint2* slotp = (uint2*)(xr + ((s - 1) % 10) * 512) + t;
            uint2 old = *slotp;
            float2 f0 = unpack2(vp0), f1 = unpack2(vp1);
            float2 o0 = unpack2(old.x), o1 = unpack2(old.y);
            sAx0 += f0.x - o0.x; sIx0 += f0.y - o0.y;
            sAx1 += f1.x - o1.x; sIx1 += f1.y - o1.y;
            *slotp = make_uint2(vp0, vp1);
            ((uint2*)(CX + (s & 1) * 520))[t] =
                make_uint2(pack2(sAx0, sIx0), pack2(sAx1, sIx1));
        }
        __syncthreads();  // colsums visible; also orders prior-phase ring reuse

        const int rY = s - 9, rX = s - 10, rC = s - 11;
        if (t < 126 && rY >= r0 && rY <= r1)
            window_pass(CY + (s & 1) * 520, YW + (rY & 3) * 512, 4 * t, 502);
        if (t >= 128 && t < 254 && rX >= r0 && rX < r1)
            window_pass(CX + (s & 1) * 520, XW + (rX & 1) * 512, 4 * (t - 128), 503);
        if (rC >= r0)
            accN += combine_row(XW + (rC & 1) * 512, YW, rC, t);

        pl = cl; pr = cr; pi = ci;
    }
    __syncthreads();
    {   // last pending x-row
        int rC = r1 - 1;
        accN += combine_row(XW + (rC & 1) * 512, YW, rC, t);
    }

    // ---- block reduce 3 accumulators -> g_part ----
#pragma unroll
    for (int o = 16; o; o >>= 1) {
        accN  += __shfl_down_sync(0xffffffffu, accN,  o);
        accDX += __shfl_down_sync(0xffffffffu, accDX, o);
        accDY += __shfl_down_sync(0xffffffffu, accDY, o);
    }
    int w = t >> 5, ln = t & 31;
    if (ln == 0) { red[w] = accN; red[8 + w] = accDX; red[16 + w] = accDY; }
    __syncthreads();
    __shared__ unsigned isLast;
    if (t == 0) {
        float n = 0, dx = 0, dy = 0;
#pragma unroll
        for (int i = 0; i < 8; i++) { n += red[i]; dx += red[8 + i]; dy += red[16 + i]; }
        float* gp = g_part[p * NB + b];
        gp[0] = n; gp[1] = dx; gp[2] = dy;
        __threadfence();
        unsigned v = atomicAdd(&g_done, 1u);
        isLast = (v == NCTA - 1) ? 1u : 0u;
    }
    __syncthreads();

    // ---- fused finalize: last CTA reduces all partials ----
    if (isLast) {
        double n = 0, dx = 0, dy = 0;
        for (int i = t; i < NCTA; i += 256) {
            n  += (double)g_part[i][0];
            dx += (double)g_part[i][1];
            dy += (double)g_part[i][2];
        }
#pragma unroll
        for (int o = 16; o; o >>= 1) {
            n  += __shfl_down_sync(0xffffffffu, n,  o);
            dx += __shfl_down_sync(0xffffffffu, dx, o);
            dy += __shfl_down_sync(0xffffffffu, dy, o);
        }
        double* dred = (double*)red;  // 8-byte aligned (word offset 15392)
        if (ln == 0) { dred[w] = n; dred[8 + w] = dx; dred[16 + w] = dy; }
        __syncthreads();
        if (t == 0) {
            double N = 0, DX = 0, DY = 0;
#pragma unroll
            for (int i = 0; i < 8; i++) { N += dred[i]; DX += dred[8 + i]; DY += dred[16 + i]; }
            out[0] = (float)(1e-4 * (N / 6060144.0) + (DX + DY) / 6279168.0);
            g_done = 0;  // reset for next graph replay
        }
    }
}

extern "C" void kernel_launch(void* const* d_in, const int* in_sizes, int n_in,
                              void* d_out, int out_size) {
    const float* out_l   = (const float*)d_in[0];
    const float* out_r   = (const float*)d_in[1];
    const float* input_i = (const float*)d_in[2];
    float* out = (float*)d_out;

    const int smem = NWORDS * (int)sizeof(float);  // 61,760 B
    cudaFuncSetAttribute(k_main, cudaFuncAttributeMaxDynamicSharedMemorySize, smem);

    k_main<<<dim3(NB, PLANES), 256, smem>>>(out_l, out_r, input_i, out);
}

// round 17
// speedup vs baseline: 4.4830x; 1.0763x over previous
#include <cuda_runtime.h>
#include <cuda_fp16.h>

// KTVLoss v5: v4 + half2-native rolling colsum accumulators (no pack/unpack/fp32
// round-trip), strength-reduced ring indexing, minimal smem zero-init.

#define NB 18
#define BROWS 28
#define PLANES 24
#define NCTA (NB * PLANES)
#define NWORDS 15440   // smem words

__device__ float g_part[NCTA][4];
__device__ unsigned g_done;   // zero-init; finalizer resets to 0 every run

__device__ __forceinline__ float2 unpack2(unsigned u) {
    __half2 h = *(__half2*)&u;
    return __half22float2(h);
}
__device__ __forceinline__ __half2 u2h(unsigned u) { return *(__half2*)&u; }
__device__ __forceinline__ unsigned h2u(__half2 h) { return *(unsigned*)&h; }

// Rolling 10-window sums (half2 lanes = A,I) over src[x0..x0+12],
// 4 outputs -> dst[x0..x0+3], bounded by limit.
__device__ __forceinline__ void window_pass(const unsigned* __restrict__ src,
                                            unsigned* __restrict__ dst,
                                            int x0, int limit) {
    uint4 q0 = *(const uint4*)(src + x0);
    uint4 q1 = *(const uint4*)(src + x0 + 4);
    uint4 q2 = *(const uint4*)(src + x0 + 8);
    unsigned e = src[x0 + 12];
    __half2 a0 = u2h(q0.x), a1 = u2h(q0.y), a2 = u2h(q0.z), a3 = u2h(q0.w);
    __half2 s = __hadd2(__hadd2(__hadd2(a0, a1), __hadd2(a2, a3)),
                __hadd2(__hadd2(__hadd2(u2h(q1.x), u2h(q1.y)),
                                __hadd2(u2h(q1.z), u2h(q1.w))),
                        __hadd2(u2h(q2.x), u2h(q2.y))));
    __half2 o0 = s;
    __half2 o1 = __hsub2(__hadd2(o0, u2h(q2.z)), a0);
    __half2 o2 = __hsub2(__hadd2(o1, u2h(q2.w)), a1);
    __half2 o3 = __hsub2(__hadd2(o2, u2h(e)), a2);
    if (x0 + 3 < limit) {
        *(uint4*)(dst + x0) = make_uint4(h2u(o0), h2u(o1), h2u(o2), h2u(o3));
    } else {
        dst[x0] = h2u(o0);
        if (x0 + 1 < limit) dst[x0 + 1] = h2u(o1);
        if (x0 + 2 < limit) dst[x0 + 2] = h2u(o2);
    }
}

// Combine flat range of x-map row rC with partner y-map values.
__device__ __forceinline__ float combine_row(const unsigned* __restrict__ xw,
                                             const unsigned* __restrict__ YW,
                                             int rC, int t) {
    float a = 0.f;
#pragma unroll
    for (int k = 0; k < 2; k++) {
        int x = t + 256 * k;
        if (x < 503) {
            float2 fx = unpack2(xw[x]);
            int j = rC + x;
            int ry = rC, cy = j;
            if (j >= 502) { ry = rC + 1; cy = j - 502; }
            float2 fy = unpack2(YW[(ry & 3) * 512 + cy]);
            a += __fdividef(fx.x + fy.x, fx.y + fy.y + 1e-4f);
        }
    }
    return a;
}

__global__ void __launch_bounds__(256, 3)
k_main(const float* __restrict__ L, const float* __restrict__ R,
       const float* __restrict__ I, float* __restrict__ out) {
    extern __shared__ float sm[];
    unsigned* xr = (unsigned*)sm;          // [10][512] vert-grad ring
    unsigned* yr = xr + 5120;              // [10][512] horiz-grad ring
    unsigned* CX = yr + 5120;              // [2][520] parity colsums
    unsigned* CY = CX + 1040;              // [2][520]
    unsigned* XW = CY + 1040;              // [2][512]
    unsigned* YW = XW + 1024;              // [4][512]
    float* red = (float*)(YW + 2048);      // 48 words (reused as 24 doubles)

    const int t = threadIdx.x;
    const int b = blockIdx.x;
    const int p = blockIdx.y;
    const int r0 = b * BROWS;
    const int r1 = min(502, r0 + BROWS);
    const bool last = (b == NB - 1);
    const int send = r1 + 9;
    const int c1 = 2 * t + 1;

    // zero only the grad rings (all other smem is written before it is read)
    for (int i = t; i < 10240; i += 256) sm[i] = 0.f;
    __syncthreads();

    const size_t pb = (size_t)p * (512 * 512);
    const float2* Lp = (const float2*)(L + pb);
    const float2* Rp = (const float2*)(R + pb);
    const float2* Ip = (const float2*)(I + pb);

    float2 nl = Lp[r0 * 256 + t], nr = Rp[r0 * 256 + t], ni = Ip[r0 * 256 + t];
    float2 pl = make_float2(0.f, 0.f), pr = pl, pi = pl;
    const __half2 hz = __floats2half2_rn(0.f, 0.f);
    __half2 colX0 = hz, colX1 = hz, colY0 = hz, colY1 = hz;  // rolling colsums
    float accN = 0, accDX = 0, accDY = 0;

    int ySlot = (r0 % 10) * 512;   // ring row offset for y push at step s
    int xSlot = 0;                 // = previous ySlot (y push of s-1)
    int cOff  = (r0 & 1) * 520;    // parity colsum offset for step s

    for (int s = r0; s <= send; ++s) {
        float2 cl = nl, cr = nr, ci = ni;
        if (s < send) {
            nl = Lp[(s + 1) * 256 + t];
            nr = Rp[(s + 1) * 256 + t];
            ni = Ip[(s + 1) * 256 + t];
        }

        // ---- vertical grads (gx row s-1), register-only ----
        __half2 vx0 = hz, vx1 = hz;
        const bool push_x = (s > r0);
        if (push_x) {
            float sl0 = cl.x - pl.x, sl1 = cl.y - pl.y;
            float sr0 = cr.x - pr.x, sr1 = cr.y - pr.y;
            float si0 = ci.x - pi.x, si1 = ci.y - pi.y;
            vx0 = __floats2half2_rn(fabsf(sl0) + fabsf(sr0), fabsf(si0));
            vx1 = __floats2half2_rn(fabsf(sl1) + fabsf(sr1), fabsf(si1));
            if ((s - 1 < r1) || (last && (s - 1) < 511))
                accDX += fabsf(sl0 + sr0 - si0) + fabsf(sl1 + sr1 - si1);
        }

        // ---- horizontal neighbor via shuffle (lane 31: global L1-hit load) ----
        float nbL = __shfl_down_sync(0xffffffffu, cl.x, 1);
        float nbR = __shfl_down_sync(0xffffffffu, cr.x, 1);
        float nbI = __shfl_down_sync(0xffffffffu, ci.x, 1);
        if ((t & 31) == 31) {
            int col = c1 + 1;
            if (col < 512) {
                size_t o = (size_t)s * 512 + col;
                nbL = ((const float*)Lp)[o];
                nbR = ((const float*)Rp)[o];
                nbI = ((const float*)Ip)[o];
            } else { nbL = cl.y; nbR = cr.y; nbI = ci.y; }  // ghost col: zero grads
        }

        float hl0 = cl.y - cl.x, hl1 = nbL - cl.y;
        float hr0 = cr.y - cr.x, hr1 = nbR - cr.y;
        float hi0 = ci.y - ci.x, hi1 = nbI - ci.y;
        if ((s < r1) || last) {
            float d0 = fabsf(hl0 + hr0 - hi0);
            float d1 = (c1 < 511) ? fabsf(hl1 + hr1 - hi1) : 0.f;
            accDY += d0 + d1;
        }

        // ---- y colsum push: half2-native rolling update ----
        {
            __half2 gy0 = __floats2half2_rn(fabsf(hl0) + fabsf(hr0), fabsf(hi0));
            __half2 gy1 = __floats2half2_rn(fabsf(hl1) + fabsf(hr1), fabsf(hi1));
            uint2* slotp = (uint2*)(yr + ySlot) + t;
            uint2 old = *slotp;
            colY0 = __hadd2(colY0, __hsub2(gy0, u2h(old.x)));
            colY1 = __hadd2(colY1, __hsub2(gy1, u2h(old.y)));
            *slotp = make_uint2(h2u(gy0), h2u(gy1));
            ((uint2*)(CY + cOff))[t] = make_uint2(h2u(colY0), h2u(colY1));
        }
        // ---- x colsum push ----
        if (push_x) {
            uint2* slotp = (uint2*)(xr + xSlot) + t;
            uint2 old = *slotp;
            colX0 = __hadd2(colX0, __hsub2(vx0, u2h(old.x)));
            colX1 = __hadd2(colX1, __hsub2(vx1, u2h(old.y)));
            *slotp = make_uint2(h2u(vx0), h2u(vx1));
            ((uint2*)(CX + cOff))[t] = make_uint2(h2u(colX0), h2u(colX1));
        }
        __syncthreads();  // colsums visible; also orders prior-phase ring reuse

        const int rY = s - 9, rX = s - 10, rC = s - 11;
        if (t < 126 && rY >= r0 && rY <= r1)
            window_pass(CY + cOff, YW + (rY & 3) * 512, 4 * t, 502);
        if (t >= 128 && t < 254 && rX >= r0 && rX < r1)
            window_pass(CX + cOff, XW + (rX & 1) * 512, 4 * (t - 128), 503);
        if (rC >= r0)
            accN += combine_row(XW + (rC & 1) * 512, YW, rC, t);

        pl = cl; pr = cr; pi = ci;
        xSlot = ySlot;
        ySlot = (ySlot == 9 * 512) ? 0 : ySlot + 512;
        cOff ^= 520;
    }
    __syncthreads();
    {   // last pending x-row
        int rC = r1 - 1;
        accN += combine_row(XW + (rC & 1) * 512, YW, rC, t);
    }

    // ---- block reduce 3 accumulators -> g_part ----
#pragma unroll
    for (int o = 16; o; o >>= 1) {
        accN  += __shfl_down_sync(0xffffffffu, accN,  o);
        accDX += __shfl_down_sync(0xffffffffu, accDX, o);
        accDY += __shfl_down_sync(0xffffffffu, accDY, o);
    }
    int w = t >> 5, ln = t & 31;
    if (ln == 0) { red[w] = accN; red[8 + w] = accDX; red[16 + w] = accDY; }
    __syncthreads();
    __shared__ unsigned isLast;
    if (t == 0) {
        float n = 0, dx = 0, dy = 0;
#pragma unroll
        for (int i = 0; i < 8; i++) { n += red[i]; dx += red[8 + i]; dy += red[16 + i]; }
        float* gp = g_part[p * NB + b];
        gp[0] = n; gp[1] = dx; gp[2] = dy;
        __threadfence();
        unsigned v = atomicAdd(&g_done, 1u);
        isLast = (v == NCTA - 1) ? 1u : 0u;
    }
    __syncthreads();

    // ---- fused finalize: last CTA reduces all partials ----
    if (isLast) {
        double n = 0, dx = 0, dy = 0;
        for (int i = t; i < NCTA; i += 256) {
            n  += (double)g_part[i][0];
            dx += (double)g_part[i][1];
            dy += (double)g_part[i][2];
        }
#pragma unroll
        for (int o = 16; o; o >>= 1) {
            n  += __shfl_down_sync(0xffffffffu, n,  o);
            dx += __shfl_down_sync(0xffffffffu, dx, o);
            dy += __shfl_down_sync(0xffffffffu, dy, o);
        }
        double* dred = (double*)red;  // 8-byte aligned (word offset 15392)
        if (ln == 0) { dred[w] = n; dred[8 + w] = dx; dred[16 + w] = dy; }
        __syncthreads();
        if (t == 0) {
            double N = 0, DX = 0, DY = 0;
#pragma unroll
            for (int i = 0; i < 8; i++) { N += dred[i]; DX += dred[8 + i]; DY += dred[16 + i]; }
            out[0] = (float)(1e-4 * (N / 6060144.0) + (DX + DY) / 6279168.0);
            g_done = 0;  // reset for next graph replay
        }
    }
}

extern "C" void kernel_launch(void* const* d_in, const int* in_sizes, int n_in,
                              void* d_out, int out_size) {
    const float* out_l   = (const float*)d_in[0];
    const float* out_r   = (const float*)d_in[1];
    const float* input_i = (const float*)d_in[2];
    float* out = (float*)d_out;

    const int smem = NWORDS * (int)sizeof(float);  // 61,760 B
    cudaFuncSetAttribute(k_main, cudaFuncAttributeMaxDynamicSharedMemorySize, smem);

    k_main<<<dim3(NB, PLANES), 256, smem>>>(out_l, out_r, input_i, out);
}